// round 14
// baseline (speedup 1.0000x reference)
#include <cuda_runtime.h>
#include <math.h>
#include <stdint.h>

#define NB_MAX 32768
#define NW 5
#define NL 20
#define WE_ 50
#define OC_ 30
#define CE_ 32
#define HID_ 100
#define TAGS_ 36
#define KPOOL 160
#define WCAP 100
#define NPOS 18

#define TM 128
#define KC 16
#define AS 132
#define NCH (KPOOL / KC)   // 10
#define NT 640

// smem float offsets for k_fc1
#define A_OFF 0                 // [2][KC][AS] = 4224 floats
#define WU_OFF 4224             // u64 SoA region: [2][1600] u64 = 6400 float-slots
#define HP_OFF 11904            // [128][101] = 12928 floats
#define WID_OFF 24832           // 640 ints
#define FC1_SMEM_FLOATS 25472   // 101888 bytes
// epilogue overlays (dead Asm/Wsm region):
#define WT_OFF 0                // [100][36] = 3600 floats
#define TMP_OFF 3600            // [128][36] = 4608 floats

// W SoA layout (u64 units, per buffer stride 1600):
//   W01: [KC][20][2]  at +0      (cols 5g+0, 5g+1)
//   W23: [KC][20][2]  at +640    (cols 5g+2, 5g+3)
//   W4 : [KC][20]     at +1280   (col  5g+4)

#define FMA2(acc, a, b) asm("fma.rn.f32x2 %0, %1, %2, %0;" : "+l"(acc) : "l"(a), "l"(b))
#define PK2(d, lo, hi) asm("mov.b64 %0, {%1, %2};" : "=l"(d) : "r"(__float_as_uint(lo)), "r"(__float_as_uint(hi)))
union F2U { unsigned long long u; float2 f; };

// ---------------- device scratch ----------------
__device__ __align__(16) float g_T[3 * 100 * 32];
__device__ __align__(16) float g_WP[NW * WCAP * 128];
__device__ __align__(16) float g_Wp[KPOOL * HID_];
__device__ __align__(16) float g_pool[NB_MAX * KPOOL];

// ---------------- K0: conv table T (smem-staged, one k per block) ----------------
__global__ __launch_bounds__(128) void k_initT(const float* __restrict__ cemb,
                                               const float* __restrict__ convw) {
    __shared__ float sc[OC_][33];   // convw[oc][ce] for this block's k (transposed)
    __shared__ float se[4][32];     // 4 cemb rows
    int tid = threadIdx.x;
    int rest0 = blockIdx.x * 4;                 // 4 consecutive (k*100+c) values, same k
    int k = rest0 / 100, cbase = rest0 - k * 100;

    for (int i = tid; i < OC_ * CE_; i += 128) {
        int oc = i >> 5, ce = i & 31;
        sc[oc][ce] = convw[(oc * CE_ + ce) * 3 + k];
    }
    se[tid >> 5][tid & 31] = cemb[(cbase + (tid >> 5)) * CE_ + (tid & 31)];
    __syncthreads();

    int oc = tid & 31, ci = tid >> 5;
    float s = 0.f;
    if (oc < OC_) {
        #pragma unroll 8
        for (int ce = 0; ce < CE_; ce++)
            s += sc[oc][ce] * se[ci][ce];
    }
    g_T[blockIdx.x * 128 + tid] = s;
}

// ---------------- K1: pool + (fused) WP/Wp builds in extra blocks ----------------
__global__ __launch_bounds__(256) void k_poolw(const int* __restrict__ inp,
        const float* __restrict__ convb, const float* __restrict__ emb,
        const float* __restrict__ fc1w, int nTasks, int nPool) {
    int blk = blockIdx.x;
    int tid = threadIdx.x;

    if (blk >= nPool) {
        int ib = blk - nPool;
        if (ib < 500) {
            __shared__ float semb[WE_];
            int w = ib / 100, c = ib - (ib / 100) * 100;
            if (tid < WE_) semb[tid] = emb[c * WE_ + tid];
            __syncthreads();
            if (tid < HID_) {
                const float* fw = fc1w + tid * 400 + w * 80;
                float s0 = 0.f, s1 = 0.f;
                #pragma unroll
                for (int d = 0; d < WE_; d += 2) {
                    s0 += semb[d] * fw[d];
                    s1 += semb[d + 1] * fw[d + 1];
                }
                g_WP[((w * WCAP + c) << 7) + tid] = s0 + s1;
            }
        } else {
            int idx = (ib - 500) * 256 + tid;
            if (idx < KPOOL * HID_) {
                int j = idx % HID_; int kk = idx / HID_;
                float v = 0.f;
                if (kk < NW * OC_) {
                    int w = kk / OC_, oc = kk % OC_;
                    v = fc1w[j * 400 + w * 80 + WE_ + oc];
                }
                g_Wp[idx] = v;
            }
        }
        return;
    }

    __shared__ int sch[32 * 21];
    int base = blk * 32;
    int lim = nTasks * 21 - base * 21;
    for (int idx = tid; idx < 32 * 21; idx += 256)
        sch[idx] = (idx < lim) ? inp[base * 21 + idx] : 0;
    __syncthreads();

    int taskL = tid >> 3;
    int oc4 = tid & 7;
    int task = base + taskL;
    if (task >= nTasks) return;

    const float4* T4 = reinterpret_cast<const float4*>(g_T);
    const int* ch = sch + taskL * 21 + 1;
    float ax = -INFINITY, ay = -INFINITY, az = -INFINITY, aw = -INFINITY;
    #pragma unroll
    for (int p = 0; p < NPOS; p++) {
        int c0 = ch[p], c1 = ch[p + 1], c2 = ch[p + 2];
        float4 t0 = T4[(0 * 100 + c0) * 8 + oc4];
        float4 t1 = T4[(1 * 100 + c1) * 8 + oc4];
        float4 t2 = T4[(2 * 100 + c2) * 8 + oc4];
        ax = fmaxf(ax, t0.x + t1.x + t2.x);
        ay = fmaxf(ay, t0.y + t1.y + t2.y);
        az = fmaxf(az, t0.z + t1.z + t2.z);
        aw = fmaxf(aw, t0.w + t1.w + t2.w);
    }
    int s = task / NW, w = task % NW;
    int oc = oc4 * 4;
    float* dst = g_pool + s * KPOOL + w * OC_ + oc;
    if (oc + 0 < OC_) dst[0] = ax + convb[oc + 0];
    if (oc + 1 < OC_) dst[1] = ay + convb[oc + 1];
    if (oc + 2 < OC_) dst[2] = az + convb[oc + 2];
    if (oc + 3 < OC_) dst[3] = aw + convb[oc + 3];
}

// ---------------- K3: fused hpart + fc1 + tanh + out ----------------
// 640 thr = 20 warps: warp = (wr 0..3 rows) x (wc 0..4 cols)
// lane = (ml 0..7 rows) x (cl 0..3 col-groups); tile 4 rows x 5 cols / thread.
// W smem is SoA (W01/W23/W4) so each warp W load = 1 wavefront.
__global__ __launch_bounds__(NT, 2) void k_fc1(
        const int* __restrict__ inp, const float* __restrict__ fc1b,
        const float* __restrict__ emb, const float* __restrict__ fc1w,
        const float* __restrict__ outw, const float* __restrict__ outb,
        float* __restrict__ out, int nB) {
    extern __shared__ float sm[];
    float* Asm = sm + A_OFF;
    unsigned long long* Wu = reinterpret_cast<unsigned long long*>(sm + WU_OFF);
    float* Hp = sm + HP_OFF;
    int* sWid = reinterpret_cast<int*>(sm + WID_OFF);

    int tid = threadIdx.x;
    int m0 = blockIdx.x * TM;

    int warp = tid >> 5, lane = tid & 31;
    int wr = warp & 3, wc = warp >> 2;
    int ml = lane & 7, cl = lane >> 3;
    int r0 = wr * 32 + ml * 4;
    int g  = wc * 4 + cl;
    int cb = g * 5;

    int rowL = tid >> 2, kpL = tid & 3;
    bool hasA = (tid < 512);
    bool hasW = (tid < 400);
    int wo0 = 0, wo1 = 0, wo2 = 0, wo3 = 0;
    if (hasW) {
        int flat = tid * 4;
        int wkk = flat / 100;
        int c0 = flat - wkk * 100;
        int wo[4];
        #pragma unroll
        for (int i = 0; i < 4; i++) {
            int c = c0 + i;
            int gg = c / 5, r = c - gg * 5;
            int o;
            if (r < 2)      o = wkk * 40 + gg * 2 + r;
            else if (r < 4) o = 640 + wkk * 40 + gg * 2 + (r - 2);
            else            o = 1280 + wkk * 20 + gg;
            wo[i] = o;
        }
        wo0 = wo[0]; wo1 = wo[1]; wo2 = wo[2]; wo3 = wo[3];
    }
    const float4* Wp4 = reinterpret_cast<const float4*>(g_Wp);

    float4 pA = make_float4(0.f, 0.f, 0.f, 0.f);
    float4 pW = make_float4(0.f, 0.f, 0.f, 0.f);

    if (hasA) {
        int m = m0 + rowL;
        if (m < nB) pA = *reinterpret_cast<const float4*>(g_pool + m * KPOOL + kpL * 4);
    }
    if (hasW) pW = Wp4[tid];
    if (hasA) {
        int b0 = (kpL * 4) * AS + rowL;
        Asm[b0] = pA.x; Asm[b0 + AS] = pA.y; Asm[b0 + 2 * AS] = pA.z; Asm[b0 + 3 * AS] = pA.w;
    }
    if (hasW) {
        unsigned long long d;
        PK2(d, pW.x, pW.x); Wu[wo0] = d;
        PK2(d, pW.y, pW.y); Wu[wo1] = d;
        PK2(d, pW.z, pW.z); Wu[wo2] = d;
        PK2(d, pW.w, pW.w); Wu[wo3] = d;
    }
    {
        int r = tid / 5, w = tid - (tid / 5) * 5;
        int m = m0 + r;
        sWid[tid] = (m < nB) ? inp[m * 105 + w * 21] : 0;
    }
    __syncthreads();

    // ---- hpart gather ----
    const float4* WP4 = reinterpret_cast<const float4*>(g_WP);
    const float4* fcb4 = reinterpret_cast<const float4*>(fc1b);
    #pragma unroll
    for (int it = 0; it < 5; it++) {
        int idx = it * NT + tid;
        int r = idx / 25, c4 = idx - (idx / 25) * 25;
        float4 acc = fcb4[c4];
        #pragma unroll
        for (int w = 0; w < NW; w++) {
            int c = sWid[r * 5 + w];
            if (c < WCAP) {
                float4 v = WP4[(w * WCAP + c) * 32 + c4];
                acc.x += v.x; acc.y += v.y; acc.z += v.z; acc.w += v.w;
            } else {
                int j0 = c4 * 4;
                for (int d = 0; d < WE_; d++) {
                    float e = emb[c * WE_ + d];
                    acc.x += e * fc1w[(j0 + 0) * 400 + w * 80 + d];
                    acc.y += e * fc1w[(j0 + 1) * 400 + w * 80 + d];
                    acc.z += e * fc1w[(j0 + 2) * 400 + w * 80 + d];
                    acc.w += e * fc1w[(j0 + 3) * 400 + w * 80 + d];
                }
            }
        }
        int b0 = r * 101 + c4 * 4;
        Hp[b0] = acc.x; Hp[b0 + 1] = acc.y; Hp[b0 + 2] = acc.z; Hp[b0 + 3] = acc.w;
    }

    // ---- mainloop ----
    unsigned long long acc2[2][5];
    #pragma unroll
    for (int i = 0; i < 2; i++)
        #pragma unroll
        for (int c = 0; c < 5; c++) acc2[i][c] = 0ull;

    for (int ck = 0; ck < NCH; ck++) {
        int b = ck & 1;
        if (ck + 1 < NCH) {
            int k0 = (ck + 1) * KC;
            if (hasA) {
                int m = m0 + rowL;
                pA = (m < nB) ? *reinterpret_cast<const float4*>(g_pool + m * KPOOL + k0 + kpL * 4)
                              : make_float4(0.f, 0.f, 0.f, 0.f);
            }
            if (hasW) pW = Wp4[(ck + 1) * 400 + tid];
        }
        const float* Ab = Asm + b * KC * AS + r0;
        const unsigned long long* Wb = Wu + b * 1600;
        #pragma unroll
        for (int kk = 0; kk < KC; kk++) {
            ulonglong2 A = *reinterpret_cast<const ulonglong2*>(Ab + kk * AS);
            ulonglong2 w01 = *reinterpret_cast<const ulonglong2*>(Wb + kk * 40 + g * 2);
            ulonglong2 w23 = *reinterpret_cast<const ulonglong2*>(Wb + 640 + kk * 40 + g * 2);
            unsigned long long w4 = Wb[1280 + kk * 20 + g];
            FMA2(acc2[0][0], A.x, w01.x); FMA2(acc2[1][0], A.y, w01.x);
            FMA2(acc2[0][1], A.x, w01.y); FMA2(acc2[1][1], A.y, w01.y);
            FMA2(acc2[0][2], A.x, w23.x); FMA2(acc2[1][2], A.y, w23.x);
            FMA2(acc2[0][3], A.x, w23.y); FMA2(acc2[1][3], A.y, w23.y);
            FMA2(acc2[0][4], A.x, w4);    FMA2(acc2[1][4], A.y, w4);
        }
        if (ck + 1 < NCH) {
            int nb = b ^ 1;
            if (hasA) {
                int b0 = nb * KC * AS + (kpL * 4) * AS + rowL;
                Asm[b0] = pA.x; Asm[b0 + AS] = pA.y; Asm[b0 + 2 * AS] = pA.z; Asm[b0 + 3 * AS] = pA.w;
            }
            if (hasW) {
                unsigned long long d;
                int o = nb * 1600;
                PK2(d, pW.x, pW.x); Wu[o + wo0] = d;
                PK2(d, pW.y, pW.y); Wu[o + wo1] = d;
                PK2(d, pW.z, pW.z); Wu[o + wo2] = d;
                PK2(d, pW.w, pW.w); Wu[o + wo3] = d;
            }
        }
        __syncthreads();
    }

    // ---- Phase B: h = tanh(acc + Hp); stage Wt ----
    float* Wt = sm + WT_OFF;
    for (int idx = tid; idx < TAGS_ * HID_; idx += NT) {
        int k = idx / TAGS_, t = idx - k * TAGS_;
        Wt[idx] = outw[t * HID_ + k];
    }
    #pragma unroll
    for (int rp = 0; rp < 2; rp++) {
        int r = r0 + rp * 2;
        #pragma unroll
        for (int c = 0; c < 5; c++) {
            F2U u; u.u = acc2[rp][c];
            Hp[r * 101 + cb + c]       = tanhf(u.f.x + Hp[r * 101 + cb + c]);
            Hp[(r + 1) * 101 + cb + c] = tanhf(u.f.y + Hp[(r + 1) * 101 + cb + c]);
        }
    }
    __syncthreads();

    // ---- Phase C: out GEMM 128x36x100 ----
    float* Tmp = sm + TMP_OFF;
    if (tid < 384) {
        int rg = tid & 63;
        int tg = tid >> 6;
        unsigned long long o0[3] = {0ull, 0ull, 0ull};
        unsigned long long o1[3] = {0ull, 0ull, 0ull};
        const float* h0p = Hp + rg * 101;
        const float* h1p = Hp + (rg + 64) * 101;
        const float* wt = Wt + tg * 6;
        #pragma unroll 4
        for (int k = 0; k < HID_; k++) {
            float h0 = h0p[k], h1 = h1p[k];
            unsigned long long hd0, hd1;
            PK2(hd0, h0, h0); PK2(hd1, h1, h1);
            const unsigned long long* wk = reinterpret_cast<const unsigned long long*>(wt + k * TAGS_);
            FMA2(o0[0], hd0, wk[0]); FMA2(o0[1], hd0, wk[1]); FMA2(o0[2], hd0, wk[2]);
            FMA2(o1[0], hd1, wk[0]); FMA2(o1[1], hd1, wk[1]); FMA2(o1[2], hd1, wk[2]);
        }
        #pragma unroll
        for (int half = 0; half < 2; half++) {
            unsigned long long* o = half ? o1 : o0;
            float* os = Tmp + (rg + half * 64) * TAGS_ + tg * 6;
            F2U q0, q1, q2; q0.u = o[0]; q1.u = o[1]; q2.u = o[2];
            os[0] = q0.f.x + outb[tg * 6 + 0];
            os[1] = q0.f.y + outb[tg * 6 + 1];
            os[2] = q1.f.x + outb[tg * 6 + 2];
            os[3] = q1.f.y + outb[tg * 6 + 3];
            os[4] = q2.f.x + outb[tg * 6 + 4];
            os[5] = q2.f.y + outb[tg * 6 + 5];
        }
    }
    __syncthreads();

    // ---- Phase D: coalesced float4 store ----
    for (int idx = tid; idx < 128 * 9; idx += NT) {
        int r = idx / 9, c = idx - r * 9;
        int m = m0 + r;
        if (m < nB)
            *reinterpret_cast<float4*>(out + m * TAGS_ + c * 4) =
                *reinterpret_cast<const float4*>(Tmp + r * TAGS_ + c * 4);
    }
}

// ---------------- launch ----------------
extern "C" void kernel_launch(void* const* d_in, const int* in_sizes, int n_in,
                              void* d_out, int out_size) {
    const int*   inp   = (const int*)  d_in[0];
    const float* emb   = (const float*)d_in[1];
    const float* cemb  = (const float*)d_in[2];
    const float* convw = (const float*)d_in[3];
    const float* convb = (const float*)d_in[4];
    const float* fc1w  = (const float*)d_in[5];
    const float* fc1b  = (const float*)d_in[6];
    const float* outw  = (const float*)d_in[7];
    const float* outb  = (const float*)d_in[8];
    float* out = (float*)d_out;

    int nB = in_sizes[0] / (NW * (1 + NL));
    if (nB > NB_MAX) nB = NB_MAX;

    int fc1_smem = FC1_SMEM_FLOATS * (int)sizeof(float);   // 101888 B
    cudaFuncSetAttribute(k_fc1, cudaFuncAttributeMaxDynamicSharedMemorySize, fc1_smem);

    k_initT<<<75, 128>>>(cemb, convw);
    int nTasks = nB * NW;
    int nPool = (nTasks + 31) / 32;
    k_poolw<<<nPool + 563, 256>>>(inp, convb, emb, fc1w, nTasks, nPool);
    k_fc1<<<(nB + TM - 1) / TM, NT, fc1_smem>>>(inp, fc1b, emb, fc1w, outw, outb, out, nB);
}

// round 15
// speedup vs baseline: 1.0386x; 1.0386x over previous
#include <cuda_runtime.h>
#include <math.h>
#include <stdint.h>

#define NB_MAX 32768
#define NW 5
#define NL 20
#define WE_ 50
#define OC_ 30
#define CE_ 32
#define HID_ 100
#define TAGS_ 36
#define KPOOL 160
#define WCAP 100
#define NPOS 18

#define TM 128
#define KC 32
#define AS 132
#define NCH (KPOOL / KC)   // 5
#define NT 640

// smem float offsets for k_fc1 (single-buffered)
#define A_OFF 0                 // [KC][AS] = 4224 floats
#define WU_OFF 4224             // u64 SoA: 3200 u64 = 6400 float-slots
#define HP_OFF 10624            // [128][101] = 12928 floats
#define WID_OFF 23552           // 640 ints
#define FC1_SMEM_FLOATS 24192   // 96768 bytes
// epilogue overlays (dead A/Wu region, 10624 floats available):
#define WT_OFF 0                // [100][36] = 3600 floats
#define TMP_OFF 3600            // [128][36] = 4608 floats

// W SoA layout (u64 units, one buffer):
//   W01: [KC][20][2]  at +0      (cols 5g+0, 5g+1)
//   W23: [KC][20][2]  at +1280   (cols 5g+2, 5g+3)
//   W4 : [KC][20]     at +2560   (col  5g+4)

#define FMA2(acc, a, b) asm("fma.rn.f32x2 %0, %1, %2, %0;" : "+l"(acc) : "l"(a), "l"(b))
#define PK2(d, lo, hi) asm("mov.b64 %0, {%1, %2};" : "=l"(d) : "r"(__float_as_uint(lo)), "r"(__float_as_uint(hi)))
union F2U { unsigned long long u; float2 f; };

// ---------------- device scratch ----------------
__device__ __align__(16) float g_T[3 * 100 * 32];
__device__ __align__(16) float g_WP[NW * WCAP * 128];
__device__ __align__(16) float g_Wp[KPOOL * HID_];
__device__ __align__(16) float g_pool[NB_MAX * KPOOL];

// ---------------- K0: conv table T (R13 simple form) ----------------
__global__ __launch_bounds__(128) void k_initT(const float* __restrict__ cemb,
                                               const float* __restrict__ convw) {
    int idx = blockIdx.x * 128 + threadIdx.x;      // grid 75*128 = 9600 exact
    int oc = idx & 31; int rest = idx >> 5; int c = rest % 100; int k = rest / 100;
    float s = 0.f;
    if (oc < OC_) {
        #pragma unroll 8
        for (int ce = 0; ce < CE_; ce++)
            s += convw[(oc * CE_ + ce) * 3 + k] * cemb[c * CE_ + ce];
    }
    g_T[idx] = s;
}

// ---------------- K1: pool + (fused) WP/Wp builds in extra blocks ----------------
__global__ __launch_bounds__(256) void k_poolw(const int* __restrict__ inp,
        const float* __restrict__ convb, const float* __restrict__ emb,
        const float* __restrict__ fc1w, int nTasks, int nPool) {
    int blk = blockIdx.x;
    int tid = threadIdx.x;

    if (blk >= nPool) {
        int ib = blk - nPool;
        if (ib < 500) {
            __shared__ float semb[WE_];
            int w = ib / 100, c = ib - (ib / 100) * 100;
            if (tid < WE_) semb[tid] = emb[c * WE_ + tid];
            __syncthreads();
            if (tid < HID_) {
                const float* fw = fc1w + tid * 400 + w * 80;
                float s0 = 0.f, s1 = 0.f;
                #pragma unroll
                for (int d = 0; d < WE_; d += 2) {
                    s0 += semb[d] * fw[d];
                    s1 += semb[d + 1] * fw[d + 1];
                }
                g_WP[((w * WCAP + c) << 7) + tid] = s0 + s1;
            }
        } else {
            int idx = (ib - 500) * 256 + tid;
            if (idx < KPOOL * HID_) {
                int j = idx % HID_; int kk = idx / HID_;
                float v = 0.f;
                if (kk < NW * OC_) {
                    int w = kk / OC_, oc = kk % OC_;
                    v = fc1w[j * 400 + w * 80 + WE_ + oc];
                }
                g_Wp[idx] = v;
            }
        }
        return;
    }

    __shared__ int sch[32 * 21];
    int base = blk * 32;
    int lim = nTasks * 21 - base * 21;
    for (int idx = tid; idx < 32 * 21; idx += 256)
        sch[idx] = (idx < lim) ? inp[base * 21 + idx] : 0;
    __syncthreads();

    int taskL = tid >> 3;
    int oc4 = tid & 7;
    int task = base + taskL;
    if (task >= nTasks) return;

    const float4* T4 = reinterpret_cast<const float4*>(g_T);
    const int* ch = sch + taskL * 21 + 1;
    float ax = -INFINITY, ay = -INFINITY, az = -INFINITY, aw = -INFINITY;
    #pragma unroll
    for (int p = 0; p < NPOS; p++) {
        int c0 = ch[p], c1 = ch[p + 1], c2 = ch[p + 2];
        float4 t0 = T4[(0 * 100 + c0) * 8 + oc4];
        float4 t1 = T4[(1 * 100 + c1) * 8 + oc4];
        float4 t2 = T4[(2 * 100 + c2) * 8 + oc4];
        ax = fmaxf(ax, t0.x + t1.x + t2.x);
        ay = fmaxf(ay, t0.y + t1.y + t2.y);
        az = fmaxf(az, t0.z + t1.z + t2.z);
        aw = fmaxf(aw, t0.w + t1.w + t2.w);
    }
    int s = task / NW, w = task % NW;
    int oc = oc4 * 4;
    float* dst = g_pool + s * KPOOL + w * OC_ + oc;
    if (oc + 0 < OC_) dst[0] = ax + convb[oc + 0];
    if (oc + 1 < OC_) dst[1] = ay + convb[oc + 1];
    if (oc + 2 < OC_) dst[2] = az + convb[oc + 2];
    if (oc + 3 < OC_) dst[3] = aw + convb[oc + 3];
}

// ---------------- K3: fused hpart + fc1 + tanh + out ----------------
// 640 thr = 20 warps: warp = (wr 0..3 rows) x (wc 0..4 cols)
// lane = (ml 0..7 rows) x (cl 0..3 col-groups); tile 4 rows x 5 cols / thread.
// Single-buffered smem, KC=32 (5 chunks): no cross-chunk register prefetch,
// keeps live regs under the 51-reg cap (2 CTAs x 640 thr).
__global__ __launch_bounds__(NT, 2) void k_fc1(
        const int* __restrict__ inp, const float* __restrict__ fc1b,
        const float* __restrict__ emb, const float* __restrict__ fc1w,
        const float* __restrict__ outw, const float* __restrict__ outb,
        float* __restrict__ out, int nB) {
    extern __shared__ float sm[];
    float* Asm = sm + A_OFF;
    unsigned long long* Wu = reinterpret_cast<unsigned long long*>(sm + WU_OFF);
    float* Hp = sm + HP_OFF;
    int* sWid = reinterpret_cast<int*>(sm + WID_OFF);

    int tid = threadIdx.x;
    int m0 = blockIdx.x * TM;

    int warp = tid >> 5, lane = tid & 31;
    int wr = warp & 3, wc = warp >> 2;
    int ml = lane & 7, cl = lane >> 3;
    int r0 = wr * 32 + ml * 4;
    int g  = wc * 4 + cl;
    int cb = g * 5;

    const float4* Wp4 = reinterpret_cast<const float4*>(g_Wp);

    // ---- chunk loader (offsets recomputed each call; no persistent regs) ----
    auto loadChunk = [&](int ck) {
        // A: [KC=32][128] transposed from g_pool rows; 1024 float4
        for (int i = tid; i < 1024; i += NT) {
            int kp = i & 7, row = i >> 3;
            int m = m0 + row;
            float4 v = (m < nB) ? *reinterpret_cast<const float4*>(g_pool + m * KPOOL + ck * KC + kp * 4)
                                : make_float4(0.f, 0.f, 0.f, 0.f);
            int b0 = (kp * 4) * AS + row;
            Asm[b0] = v.x; Asm[b0 + AS] = v.y; Asm[b0 + 2 * AS] = v.z; Asm[b0 + 3 * AS] = v.w;
        }
        // W: 800 float4, store duplicated into SoA u64 layout
        for (int i = tid; i < 800; i += NT) {
            float4 v = Wp4[ck * 800 + i];
            int flat = i * 4;
            int wkk = flat / 100;
            int c0 = flat - wkk * 100;
            float vv[4] = {v.x, v.y, v.z, v.w};
            #pragma unroll
            for (int q = 0; q < 4; q++) {
                int c = c0 + q;
                int gg = c / 5, r = c - gg * 5;
                int o;
                if (r < 2)      o = wkk * 40 + gg * 2 + r;
                else if (r < 4) o = 1280 + wkk * 40 + gg * 2 + (r - 2);
                else            o = 2560 + wkk * 20 + gg;
                unsigned long long d; PK2(d, vv[q], vv[q]);
                Wu[o] = d;
            }
        }
    };

    // ---- prologue: word ids + chunk0 loads (overlap with gather) ----
    {
        int r = tid / 5, w = tid - (tid / 5) * 5;
        int m = m0 + r;
        sWid[tid] = (m < nB) ? inp[m * 105 + w * 21] : 0;
    }
    loadChunk(0);
    __syncthreads();

    // ---- hpart gather ----
    const float4* WP4 = reinterpret_cast<const float4*>(g_WP);
    const float4* fcb4 = reinterpret_cast<const float4*>(fc1b);
    #pragma unroll
    for (int it = 0; it < 5; it++) {
        int idx = it * NT + tid;
        int r = idx / 25, c4 = idx - (idx / 25) * 25;
        float4 acc = fcb4[c4];
        #pragma unroll
        for (int w = 0; w < NW; w++) {
            int c = sWid[r * 5 + w];
            if (c < WCAP) {
                float4 v = WP4[(w * WCAP + c) * 32 + c4];
                acc.x += v.x; acc.y += v.y; acc.z += v.z; acc.w += v.w;
            } else {
                int j0 = c4 * 4;
                for (int d = 0; d < WE_; d++) {
                    float e = emb[c * WE_ + d];
                    acc.x += e * fc1w[(j0 + 0) * 400 + w * 80 + d];
                    acc.y += e * fc1w[(j0 + 1) * 400 + w * 80 + d];
                    acc.z += e * fc1w[(j0 + 2) * 400 + w * 80 + d];
                    acc.w += e * fc1w[(j0 + 3) * 400 + w * 80 + d];
                }
            }
        }
        int b0 = r * 101 + c4 * 4;
        Hp[b0] = acc.x; Hp[b0 + 1] = acc.y; Hp[b0 + 2] = acc.z; Hp[b0 + 3] = acc.w;
    }

    // ---- mainloop: 5 chunks of KC=32, single buffer ----
    unsigned long long acc2[2][5];
    #pragma unroll
    for (int i = 0; i < 2; i++)
        #pragma unroll
        for (int c = 0; c < 5; c++) acc2[i][c] = 0ull;

    for (int ck = 0; ck < NCH; ck++) {
        if (ck) {
            __syncthreads();      // prev compute done before overwrite
            loadChunk(ck);
            __syncthreads();      // chunk visible
        }
        const float* Ab = Asm + r0;
        #pragma unroll
        for (int kk = 0; kk < KC; kk++) {
            ulonglong2 A = *reinterpret_cast<const ulonglong2*>(Ab + kk * AS);
            ulonglong2 w01 = *reinterpret_cast<const ulonglong2*>(Wu + kk * 40 + g * 2);
            ulonglong2 w23 = *reinterpret_cast<const ulonglong2*>(Wu + 1280 + kk * 40 + g * 2);
            unsigned long long w4 = Wu[2560 + kk * 20 + g];
            FMA2(acc2[0][0], A.x, w01.x); FMA2(acc2[1][0], A.y, w01.x);
            FMA2(acc2[0][1], A.x, w01.y); FMA2(acc2[1][1], A.y, w01.y);
            FMA2(acc2[0][2], A.x, w23.x); FMA2(acc2[1][2], A.y, w23.x);
            FMA2(acc2[0][3], A.x, w23.y); FMA2(acc2[1][3], A.y, w23.y);
            FMA2(acc2[0][4], A.x, w4);    FMA2(acc2[1][4], A.y, w4);
        }
    }
    __syncthreads();   // mainloop done; A/Wu region becomes epilogue scratch

    // ---- Phase B: h = tanh(acc + Hp); stage Wt ----
    float* Wt = sm + WT_OFF;
    for (int idx = tid; idx < TAGS_ * HID_; idx += NT) {
        int k = idx / TAGS_, t = idx - k * TAGS_;
        Wt[idx] = outw[t * HID_ + k];
    }
    #pragma unroll
    for (int rp = 0; rp < 2; rp++) {
        int r = r0 + rp * 2;
        #pragma unroll
        for (int c = 0; c < 5; c++) {
            F2U u; u.u = acc2[rp][c];
            Hp[r * 101 + cb + c]       = tanhf(u.f.x + Hp[r * 101 + cb + c]);
            Hp[(r + 1) * 101 + cb + c] = tanhf(u.f.y + Hp[(r + 1) * 101 + cb + c]);
        }
    }
    __syncthreads();

    // ---- Phase C: out GEMM 128x36x100 ----
    float* Tmp = sm + TMP_OFF;
    if (tid < 384) {
        int rg = tid & 63;
        int tg = tid >> 6;
        unsigned long long o0[3] = {0ull, 0ull, 0ull};
        unsigned long long o1[3] = {0ull, 0ull, 0ull};
        const float* h0p = Hp + rg * 101;
        const float* h1p = Hp + (rg + 64) * 101;
        const float* wt = Wt + tg * 6;
        #pragma unroll 4
        for (int k = 0; k < HID_; k++) {
            float h0 = h0p[k], h1 = h1p[k];
            unsigned long long hd0, hd1;
            PK2(hd0, h0, h0); PK2(hd1, h1, h1);
            const unsigned long long* wk = reinterpret_cast<const unsigned long long*>(wt + k * TAGS_);
            FMA2(o0[0], hd0, wk[0]); FMA2(o0[1], hd0, wk[1]); FMA2(o0[2], hd0, wk[2]);
            FMA2(o1[0], hd1, wk[0]); FMA2(o1[1], hd1, wk[1]); FMA2(o1[2], hd1, wk[2]);
        }
        #pragma unroll
        for (int half = 0; half < 2; half++) {
            unsigned long long* o = half ? o1 : o0;
            float* os = Tmp + (rg + half * 64) * TAGS_ + tg * 6;
            F2U q0, q1, q2; q0.u = o[0]; q1.u = o[1]; q2.u = o[2];
            os[0] = q0.f.x + outb[tg * 6 + 0];
            os[1] = q0.f.y + outb[tg * 6 + 1];
            os[2] = q1.f.x + outb[tg * 6 + 2];
            os[3] = q1.f.y + outb[tg * 6 + 3];
            os[4] = q2.f.x + outb[tg * 6 + 4];
            os[5] = q2.f.y + outb[tg * 6 + 5];
        }
    }
    __syncthreads();

    // ---- Phase D: coalesced float4 store ----
    for (int idx = tid; idx < 128 * 9; idx += NT) {
        int r = idx / 9, c = idx - r * 9;
        int m = m0 + r;
        if (m < nB)
            *reinterpret_cast<float4*>(out + m * TAGS_ + c * 4) =
                *reinterpret_cast<const float4*>(Tmp + r * TAGS_ + c * 4);
    }
}

// ---------------- launch ----------------
extern "C" void kernel_launch(void* const* d_in, const int* in_sizes, int n_in,
                              void* d_out, int out_size) {
    const int*   inp   = (const int*)  d_in[0];
    const float* emb   = (const float*)d_in[1];
    const float* cemb  = (const float*)d_in[2];
    const float* convw = (const float*)d_in[3];
    const float* convb = (const float*)d_in[4];
    const float* fc1w  = (const float*)d_in[5];
    const float* fc1b  = (const float*)d_in[6];
    const float* outw  = (const float*)d_in[7];
    const float* outb  = (const float*)d_in[8];
    float* out = (float*)d_out;

    int nB = in_sizes[0] / (NW * (1 + NL));
    if (nB > NB_MAX) nB = NB_MAX;

    int fc1_smem = FC1_SMEM_FLOATS * (int)sizeof(float);   // 96768 B
    cudaFuncSetAttribute(k_fc1, cudaFuncAttributeMaxDynamicSharedMemorySize, fc1_smem);

    k_initT<<<75, 128>>>(cemb, convw);
    int nTasks = nB * NW;
    int nPool = (nTasks + 31) / 32;
    k_poolw<<<nPool + 563, 256>>>(inp, convb, emb, fc1w, nTasks, nPool);
    k_fc1<<<(nB + TM - 1) / TM, NT, fc1_smem>>>(inp, fc1b, emb, fc1w, outw, outb, out, nB);
}

// round 16
// speedup vs baseline: 1.1485x; 1.1059x over previous
#include <cuda_runtime.h>
#include <cuda_fp16.h>
#include <math.h>
#include <stdint.h>

#define NB_MAX 32768
#define NW 5
#define NL 20
#define WE_ 50
#define OC_ 30
#define CE_ 32
#define HID_ 100
#define TAGS_ 36
#define KPOOL 160
#define WCAP 100
#define NPOS 18

#define TM 128
#define KC 32
#define AS 132
#define NCH (KPOOL / KC)   // 5
#define NT 640
#define NPOOLB 592         // persistent pool blocks

// smem float offsets for k_fc1 (single-buffered)
#define A_OFF 0                 // [KC][AS] = 4224 floats
#define WU_OFF 4224             // u64 SoA: 3200 u64 = 6400 float-slots
#define HP_OFF 10624            // [128][101] = 12928 floats
#define WID_OFF 23552           // 640 ints
#define FC1_SMEM_FLOATS 24192   // 96768 bytes
#define WT_OFF 0                // epilogue overlay
#define TMP_OFF 3600

#define FMA2(acc, a, b) asm("fma.rn.f32x2 %0, %1, %2, %0;" : "+l"(acc) : "l"(a), "l"(b))
#define PK2(d, lo, hi) asm("mov.b64 %0, {%1, %2};" : "=l"(d) : "r"(__float_as_uint(lo)), "r"(__float_as_uint(hi)))
union F2U { unsigned long long u; float2 f; };

// ---------------- device scratch ----------------
// T table, fp16, duplicated per bank-parity: halves layout ((k*100+c)*2 + dup)*32 + oc
__device__ __align__(16) __half g_Th[3 * 100 * 2 * 32];
__device__ __align__(16) float g_WP[NW * WCAP * 128];
__device__ __align__(16) float g_Wp[KPOOL * HID_];
__device__ __align__(16) float g_pool[NB_MAX * KPOOL];

// ---------------- K0: conv table T (fp16, dup copies) ----------------
__global__ __launch_bounds__(128) void k_initT(const float* __restrict__ cemb,
                                               const float* __restrict__ convw) {
    int idx = blockIdx.x * 128 + threadIdx.x;      // grid 75*128 = 9600 exact
    int oc = idx & 31; int rest = idx >> 5; int c = rest % 100; int k = rest / 100;
    float s = 0.f;
    if (oc < OC_) {
        #pragma unroll 8
        for (int ce = 0; ce < CE_; ce++)
            s += convw[(oc * CE_ + ce) * 3 + k] * cemb[c * CE_ + ce];
    }
    __half h = __float2half(s);
    int b = (k * 100 + c) * 64 + oc;
    g_Th[b] = h;
    g_Th[b + 32] = h;
}

// ---------------- K1: persistent pool (smem fp16 T) + fused WP/Wp builds ----------------
__global__ __launch_bounds__(256) void k_poolw(const int* __restrict__ inp,
        const float* __restrict__ convb, const float* __restrict__ emb,
        const float* __restrict__ fc1w, int nTasks) {
    __shared__ __align__(16) __half sTh[3 * 100 * 2 * 32];   // 38400 B
    __shared__ int sch[32 * 21];                             // 2688 B
    __shared__ float semb[WE_];

    int blk = blockIdx.x;
    int tid = threadIdx.x;

    if (blk >= NPOOLB) {
        // -------- init-W blocks (no dependency on T/pool) --------
        int ib = blk - NPOOLB;
        if (ib < 500) {
            int w = ib / 100, c = ib - (ib / 100) * 100;
            if (tid < WE_) semb[tid] = emb[c * WE_ + tid];
            __syncthreads();
            if (tid < HID_) {
                const float* fw = fc1w + tid * 400 + w * 80;
                float s0 = 0.f, s1 = 0.f;
                #pragma unroll
                for (int d = 0; d < WE_; d += 2) {
                    s0 += semb[d] * fw[d];
                    s1 += semb[d + 1] * fw[d + 1];
                }
                g_WP[((w * WCAP + c) << 7) + tid] = s0 + s1;
            }
        } else {
            int idx = (ib - 500) * 256 + tid;
            if (idx < KPOOL * HID_) {
                int j = idx % HID_; int kk = idx / HID_;
                float v = 0.f;
                if (kk < NW * OC_) {
                    int w = kk / OC_, oc = kk % OC_;
                    v = fc1w[j * 400 + w * 80 + WE_ + oc];
                }
                g_Wp[idx] = v;
            }
        }
        return;
    }

    // -------- stage fp16 T into smem (2400 uint4) --------
    {
        const uint4* src = reinterpret_cast<const uint4*>(g_Th);
        uint4* dst = reinterpret_cast<uint4*>(sTh);
        for (int i = tid; i < 2400; i += 256) dst[i] = src[i];
    }
    __syncthreads();

    int taskL = tid >> 3;          // 0..31 tasks per batch
    int lane3 = tid & 7;           // 4 oc each (oc = lane3*4)
    int dl = (taskL & 1) * 16 + lane3 * 2;   // dup + lane offset, half2 units
    const __half2* T2 = reinterpret_cast<const __half2*>(sTh);

    for (int base = blk * 32; base < nTasks; base += NPOOLB * 32) {
        __syncthreads();   // protect sch reuse
        int lim = nTasks * 21 - base * 21;
        for (int idx = tid; idx < 32 * 21; idx += 256)
            sch[idx] = (idx < lim) ? inp[base * 21 + idx] : 0;
        __syncthreads();

        int task = base + taskL;
        const int* ch = sch + taskL * 21 + 1;

        half2 mx0 = __float2half2_rn(-60000.0f);
        half2 mx1 = mx0;
        half2 P1a, P1b, P2a, P2b;

        // j=0: only t0
        {
            int c = ch[0];
            uint2 v0 = *reinterpret_cast<const uint2*>(T2 + (c * 32 + dl));
            P1a = *reinterpret_cast<half2*>(&v0.x); P1b = *reinterpret_cast<half2*>(&v0.y);
        }
        // j=1: t0, t1
        {
            int c = ch[1];
            uint2 v0 = *reinterpret_cast<const uint2*>(T2 + (c * 32 + dl));
            uint2 v1 = *reinterpret_cast<const uint2*>(T2 + (3200 + c * 32 + dl));
            P2a = __hadd2(P1a, *reinterpret_cast<half2*>(&v1.x));
            P2b = __hadd2(P1b, *reinterpret_cast<half2*>(&v1.y));
            P1a = *reinterpret_cast<half2*>(&v0.x); P1b = *reinterpret_cast<half2*>(&v0.y);
        }
        // j=2..18: complete pos j-2, roll window
        #pragma unroll
        for (int j = 2; j <= 18; j++) {
            int c = ch[j];
            uint2 v0 = *reinterpret_cast<const uint2*>(T2 + (c * 32 + dl));
            uint2 v1 = *reinterpret_cast<const uint2*>(T2 + (3200 + c * 32 + dl));
            uint2 v2 = *reinterpret_cast<const uint2*>(T2 + (6400 + c * 32 + dl));
            mx0 = __hmax2(mx0, __hadd2(P2a, *reinterpret_cast<half2*>(&v2.x)));
            mx1 = __hmax2(mx1, __hadd2(P2b, *reinterpret_cast<half2*>(&v2.y)));
            P2a = __hadd2(P1a, *reinterpret_cast<half2*>(&v1.x));
            P2b = __hadd2(P1b, *reinterpret_cast<half2*>(&v1.y));
            P1a = *reinterpret_cast<half2*>(&v0.x); P1b = *reinterpret_cast<half2*>(&v0.y);
        }
        // j=19: only t2, complete pos 17
        {
            int c = ch[19];
            uint2 v2 = *reinterpret_cast<const uint2*>(T2 + (6400 + c * 32 + dl));
            mx0 = __hmax2(mx0, __hadd2(P2a, *reinterpret_cast<half2*>(&v2.x)));
            mx1 = __hmax2(mx1, __hadd2(P2b, *reinterpret_cast<half2*>(&v2.y)));
        }

        if (task < nTasks) {
            float2 f0 = __half22float2(mx0);   // oc, oc+1
            float2 f1 = __half22float2(mx1);   // oc+2, oc+3
            int s = task / NW, w = task - (task / NW) * NW;
            int oc = lane3 * 4;
            float* dst = g_pool + s * KPOOL + w * OC_ + oc;
            if (oc < 28) {
                *reinterpret_cast<float2*>(dst) =
                    make_float2(f0.x + convb[oc], f0.y + convb[oc + 1]);
                *reinterpret_cast<float2*>(dst + 2) =
                    make_float2(f1.x + convb[oc + 2], f1.y + convb[oc + 3]);
            } else {   // oc == 28: only 28,29 valid
                *reinterpret_cast<float2*>(dst) =
                    make_float2(f0.x + convb[28], f0.y + convb[29]);
            }
        }
    }
}

// ---------------- K3: fused hpart + fc1 + tanh + out (R15, unchanged) ----------------
__global__ __launch_bounds__(NT, 2) void k_fc1(
        const int* __restrict__ inp, const float* __restrict__ fc1b,
        const float* __restrict__ emb, const float* __restrict__ fc1w,
        const float* __restrict__ outw, const float* __restrict__ outb,
        float* __restrict__ out, int nB) {
    extern __shared__ float sm[];
    float* Asm = sm + A_OFF;
    unsigned long long* Wu = reinterpret_cast<unsigned long long*>(sm + WU_OFF);
    float* Hp = sm + HP_OFF;
    int* sWid = reinterpret_cast<int*>(sm + WID_OFF);

    int tid = threadIdx.x;
    int m0 = blockIdx.x * TM;

    int warp = tid >> 5, lane = tid & 31;
    int wr = warp & 3, wc = warp >> 2;
    int ml = lane & 7, cl = lane >> 3;
    int r0 = wr * 32 + ml * 4;
    int g  = wc * 4 + cl;
    int cb = g * 5;

    const float4* Wp4 = reinterpret_cast<const float4*>(g_Wp);

    auto loadChunk = [&](int ck) {
        for (int i = tid; i < 1024; i += NT) {
            int kp = i & 7, row = i >> 3;
            int m = m0 + row;
            float4 v = (m < nB) ? *reinterpret_cast<const float4*>(g_pool + m * KPOOL + ck * KC + kp * 4)
                                : make_float4(0.f, 0.f, 0.f, 0.f);
            int b0 = (kp * 4) * AS + row;
            Asm[b0] = v.x; Asm[b0 + AS] = v.y; Asm[b0 + 2 * AS] = v.z; Asm[b0 + 3 * AS] = v.w;
        }
        for (int i = tid; i < 800; i += NT) {
            float4 v = Wp4[ck * 800 + i];
            int flat = i * 4;
            int wkk = flat / 100;
            int c0 = flat - wkk * 100;
            float vv[4] = {v.x, v.y, v.z, v.w};
            #pragma unroll
            for (int q = 0; q < 4; q++) {
                int c = c0 + q;
                int gg = c / 5, r = c - gg * 5;
                int o;
                if (r < 2)      o = wkk * 40 + gg * 2 + r;
                else if (r < 4) o = 1280 + wkk * 40 + gg * 2 + (r - 2);
                else            o = 2560 + wkk * 20 + gg;
                unsigned long long d; PK2(d, vv[q], vv[q]);
                Wu[o] = d;
            }
        }
    };

    {
        int r = tid / 5, w = tid - (tid / 5) * 5;
        int m = m0 + r;
        sWid[tid] = (m < nB) ? inp[m * 105 + w * 21] : 0;
    }
    loadChunk(0);
    __syncthreads();

    const float4* WP4 = reinterpret_cast<const float4*>(g_WP);
    const float4* fcb4 = reinterpret_cast<const float4*>(fc1b);
    #pragma unroll
    for (int it = 0; it < 5; it++) {
        int idx = it * NT + tid;
        int r = idx / 25, c4 = idx - (idx / 25) * 25;
        float4 acc = fcb4[c4];
        #pragma unroll
        for (int w = 0; w < NW; w++) {
            int c = sWid[r * 5 + w];
            if (c < WCAP) {
                float4 v = WP4[(w * WCAP + c) * 32 + c4];
                acc.x += v.x; acc.y += v.y; acc.z += v.z; acc.w += v.w;
            } else {
                int j0 = c4 * 4;
                for (int d = 0; d < WE_; d++) {
                    float e = emb[c * WE_ + d];
                    acc.x += e * fc1w[(j0 + 0) * 400 + w * 80 + d];
                    acc.y += e * fc1w[(j0 + 1) * 400 + w * 80 + d];
                    acc.z += e * fc1w[(j0 + 2) * 400 + w * 80 + d];
                    acc.w += e * fc1w[(j0 + 3) * 400 + w * 80 + d];
                }
            }
        }
        int b0 = r * 101 + c4 * 4;
        Hp[b0] = acc.x; Hp[b0 + 1] = acc.y; Hp[b0 + 2] = acc.z; Hp[b0 + 3] = acc.w;
    }

    unsigned long long acc2[2][5];
    #pragma unroll
    for (int i = 0; i < 2; i++)
        #pragma unroll
        for (int c = 0; c < 5; c++) acc2[i][c] = 0ull;

    for (int ck = 0; ck < NCH; ck++) {
        if (ck) {
            __syncthreads();
            loadChunk(ck);
            __syncthreads();
        }
        const float* Ab = Asm + r0;
        #pragma unroll
        for (int kk = 0; kk < KC; kk++) {
            ulonglong2 A = *reinterpret_cast<const ulonglong2*>(Ab + kk * AS);
            ulonglong2 w01 = *reinterpret_cast<const ulonglong2*>(Wu + kk * 40 + g * 2);
            ulonglong2 w23 = *reinterpret_cast<const ulonglong2*>(Wu + 1280 + kk * 40 + g * 2);
            unsigned long long w4 = Wu[2560 + kk * 20 + g];
            FMA2(acc2[0][0], A.x, w01.x); FMA2(acc2[1][0], A.y, w01.x);
            FMA2(acc2[0][1], A.x, w01.y); FMA2(acc2[1][1], A.y, w01.y);
            FMA2(acc2[0][2], A.x, w23.x); FMA2(acc2[1][2], A.y, w23.x);
            FMA2(acc2[0][3], A.x, w23.y); FMA2(acc2[1][3], A.y, w23.y);
            FMA2(acc2[0][4], A.x, w4);    FMA2(acc2[1][4], A.y, w4);
        }
    }
    __syncthreads();

    float* Wt = sm + WT_OFF;
    for (int idx = tid; idx < TAGS_ * HID_; idx += NT) {
        int k = idx / TAGS_, t = idx - k * TAGS_;
        Wt[idx] = outw[t * HID_ + k];
    }
    #pragma unroll
    for (int rp = 0; rp < 2; rp++) {
        int r = r0 + rp * 2;
        #pragma unroll
        for (int c = 0; c < 5; c++) {
            F2U u; u.u = acc2[rp][c];
            Hp[r * 101 + cb + c]       = tanhf(u.f.x + Hp[r * 101 + cb + c]);
            Hp[(r + 1) * 101 + cb + c] = tanhf(u.f.y + Hp[(r + 1) * 101 + cb + c]);
        }
    }
    __syncthreads();

    float* Tmp = sm + TMP_OFF;
    if (tid < 384) {
        int rg = tid & 63;
        int tg = tid >> 6;
        unsigned long long o0[3] = {0ull, 0ull, 0ull};
        unsigned long long o1[3] = {0ull, 0ull, 0ull};
        const float* h0p = Hp + rg * 101;
        const float* h1p = Hp + (rg + 64) * 101;
        const float* wt = Wt + tg * 6;
        #pragma unroll 4
        for (int k = 0; k < HID_; k++) {
            float h0 = h0p[k], h1 = h1p[k];
            unsigned long long hd0, hd1;
            PK2(hd0, h0, h0); PK2(hd1, h1, h1);
            const unsigned long long* wk = reinterpret_cast<const unsigned long long*>(wt + k * TAGS_);
            FMA2(o0[0], hd0, wk[0]); FMA2(o0[1], hd0, wk[1]); FMA2(o0[2], hd0, wk[2]);
            FMA2(o1[0], hd1, wk[0]); FMA2(o1[1], hd1, wk[1]); FMA2(o1[2], hd1, wk[2]);
        }
        #pragma unroll
        for (int half = 0; half < 2; half++) {
            unsigned long long* o = half ? o1 : o0;
            float* os = Tmp + (rg + half * 64) * TAGS_ + tg * 6;
            F2U q0, q1, q2; q0.u = o[0]; q1.u = o[1]; q2.u = o[2];
            os[0] = q0.f.x + outb[tg * 6 + 0];
            os[1] = q0.f.y + outb[tg * 6 + 1];
            os[2] = q1.f.x + outb[tg * 6 + 2];
            os[3] = q1.f.y + outb[tg * 6 + 3];
            os[4] = q2.f.x + outb[tg * 6 + 4];
            os[5] = q2.f.y + outb[tg * 6 + 5];
        }
    }
    __syncthreads();

    for (int idx = tid; idx < 128 * 9; idx += NT) {
        int r = idx / 9, c = idx - r * 9;
        int m = m0 + r;
        if (m < nB)
            *reinterpret_cast<float4*>(out + m * TAGS_ + c * 4) =
                *reinterpret_cast<const float4*>(Tmp + r * TAGS_ + c * 4);
    }
}

// ---------------- launch ----------------
extern "C" void kernel_launch(void* const* d_in, const int* in_sizes, int n_in,
                              void* d_out, int out_size) {
    const int*   inp   = (const int*)  d_in[0];
    const float* emb   = (const float*)d_in[1];
    const float* cemb  = (const float*)d_in[2];
    const float* convw = (const float*)d_in[3];
    const float* convb = (const float*)d_in[4];
    const float* fc1w  = (const float*)d_in[5];
    const float* fc1b  = (const float*)d_in[6];
    const float* outw  = (const float*)d_in[7];
    const float* outb  = (const float*)d_in[8];
    float* out = (float*)d_out;

    int nB = in_sizes[0] / (NW * (1 + NL));
    if (nB > NB_MAX) nB = NB_MAX;

    int fc1_smem = FC1_SMEM_FLOATS * (int)sizeof(float);   // 96768 B
    cudaFuncSetAttribute(k_fc1, cudaFuncAttributeMaxDynamicSharedMemorySize, fc1_smem);

    k_initT<<<75, 128>>>(cemb, convw);
    int nTasks = nB * NW;
    k_poolw<<<NPOOLB + 563, 256>>>(inp, convb, emb, fc1w, nTasks);
    k_fc1<<<(nB + TM - 1) / TM, NT, fc1_smem>>>(inp, fc1b, emb, fc1w, outw, outb, out, nB);
}